// round 17
// baseline (speedup 1.0000x reference)
#include <cuda_runtime.h>
#include <cuda_bf16.h>
#include <cstdint>

#define CD  512
#define SD  1024
#define NHD 8
#define HD  64
#define NTOK 8192

// ---------------------------------------------------------------------------
// Split-bf16 scratch (device globals; no allocation allowed).
// ---------------------------------------------------------------------------
__device__ __nv_bfloat16 g_xh[NTOK * CD];
__device__ __nv_bfloat16 g_xl[NTOK * CD];
__device__ __nv_bfloat16 g_wh[4 * CD * CD];
__device__ __nv_bfloat16 g_wl[4 * CD * CD];
__device__ __nv_bfloat16 g_qh[64 * SD * HD];
__device__ __nv_bfloat16 g_ql[64 * SD * HD];
__device__ __nv_bfloat16 g_kh[64 * SD * HD];
__device__ __nv_bfloat16 g_kl[64 * SD * HD];
__device__ __nv_bfloat16 g_vh[64 * SD * HD];
__device__ __nv_bfloat16 g_vl[64 * SD * HD];
__device__ __nv_bfloat16 g_aoh[NTOK * CD];
__device__ __nv_bfloat16 g_aol[NTOK * CD];

__device__ __forceinline__ uint32_t pack_bf2(__nv_bfloat16 a, __nv_bfloat16 b) {
    return (uint32_t)__bfloat16_as_ushort(a) | ((uint32_t)__bfloat16_as_ushort(b) << 16);
}
__device__ __forceinline__ void split2(float v0, float v1, uint32_t& hi, uint32_t& lo) {
    __nv_bfloat16 h0 = __float2bfloat16(v0);
    __nv_bfloat16 h1 = __float2bfloat16(v1);
    __nv_bfloat16 l0 = __float2bfloat16(v0 - __bfloat162float(h0));
    __nv_bfloat16 l1 = __float2bfloat16(v1 - __bfloat162float(h1));
    hi = pack_bf2(h0, h1);
    lo = pack_bf2(l0, l1);
}
__device__ __forceinline__ uint32_t smem_u32(const void* p) {
    uint32_t a;
    asm("{ .reg .u64 t; cvta.to.shared.u64 t, %1; cvt.u32.u64 %0, t; }" : "=r"(a) : "l"(p));
    return a;
}
__device__ __forceinline__ void cp16(uint32_t dst, const void* src) {
    asm volatile("cp.async.cg.shared.global [%0], [%1], 16;" :: "r"(dst), "l"(src));
}
#define CP_COMMIT() asm volatile("cp.async.commit_group;" ::: "memory")
#define CP_WAIT1()  asm volatile("cp.async.wait_group 1;" ::: "memory")

#define LDSM4(r0, r1, r2, r3, a) \
    asm volatile("ldmatrix.sync.aligned.m8n8.x4.shared.b16 {%0,%1,%2,%3}, [%4];" \
        : "=r"(r0), "=r"(r1), "=r"(r2), "=r"(r3) : "r"(a))
#define LDSM4T(r0, r1, r2, r3, a) \
    asm volatile("ldmatrix.sync.aligned.m8n8.x4.trans.shared.b16 {%0,%1,%2,%3}, [%4];" \
        : "=r"(r0), "=r"(r1), "=r"(r2), "=r"(r3) : "r"(a))
#define MMA16816(c, a0, a1, a2, a3, b0, b1) \
    asm volatile("mma.sync.aligned.m16n8k16.row.col.f32.bf16.bf16.f32 " \
        "{%0,%1,%2,%3}, {%4,%5,%6,%7}, {%8,%9}, {%0,%1,%2,%3};" \
        : "+f"((c)[0]), "+f"((c)[1]), "+f"((c)[2]), "+f"((c)[3]) \
        : "r"(a0), "r"(a1), "r"(a2), "r"(a3), "r"(b0), "r"(b1))

// ---------------------------------------------------------------------------
// Pre-split kernels (unchanged)
// ---------------------------------------------------------------------------
__global__ __launch_bounds__(256) void split_w(
    const float* __restrict__ Wq, const float* __restrict__ Wk,
    const float* __restrict__ Wv, const float* __restrict__ Wo)
{
    int idx = blockIdx.x * 256 + threadIdx.x;
#pragma unroll
    for (int p = 0; p < 4; ++p) {
        int pair = idx * 4 + p;
        int mat = pair >> 17;
        int off = (pair & 131071) * 2;
        const float* W = (mat == 0) ? Wq : (mat == 1) ? Wk : (mat == 2) ? Wv : Wo;
        float v0 = W[off], v1 = W[off + 1];
        uint32_t hi, lo; split2(v0, v1, hi, lo);
        *(uint32_t*)(g_wh + (size_t)mat * 262144 + off) = hi;
        *(uint32_t*)(g_wl + (size_t)mat * 262144 + off) = lo;
    }
}

__global__ __launch_bounds__(256) void split_x(const float* __restrict__ x)
{
    __shared__ float t[32][33];
    const int n = blockIdx.z, k0 = blockIdx.x * 32, s0 = blockIdx.y * 32;
    const int tx = threadIdx.x & 31, ty = threadIdx.x >> 5;
    const float* xb = x + ((size_t)n * CD + k0) * SD + s0;
#pragma unroll
    for (int i = 0; i < 4; ++i)
        t[ty * 4 + i][tx] = xb[(ty * 4 + i) * SD + tx];
    __syncthreads();
    const int r = threadIdx.x >> 3;
    const int kk = (threadIdx.x & 7) * 4;
    float v0 = t[kk][r], v1 = t[kk + 1][r], v2 = t[kk + 2][r], v3 = t[kk + 3][r];
    uint32_t h0, l0, h1, l1;
    split2(v0, v1, h0, l0);
    split2(v2, v3, h1, l1);
    size_t base = ((size_t)n * SD + s0 + r) * CD + k0 + kk;
    *(uint32_t*)(g_xh + base) = h0; *(uint32_t*)(g_xh + base + 2) = h1;
    *(uint32_t*)(g_xl + base) = l0; *(uint32_t*)(g_xl + base + 2) = l1;
}

// ---------------------------------------------------------------------------
// GEMM smem: k-chunk 32, double-buffered, raw mma.sync.
// Per buffer: Ah[128][40] (10240B) Al (10240B) Bh[64][40] (5120B) Bl (5120B)
//   = 30720B; x2 buffers = 61440B. Epilogue reuse: f32 [128][68] = 34816B.
// Block 128m x 64n, 8 warps (wm=w>>1: 32-row band, wn=w&1: 32-col half).
// Warp tile 32x32 = 2 m-tiles(16) x 4 n-tiles(8); acc[2][4][4] = 32 regs.
// ---------------------------------------------------------------------------
#define GM_BUF   30720
#define GM_AL    10240
#define GM_B     20480
#define GM_BL    5120
#define GM_SMEM  61440

// Shared GEMM mainloop body as a macro-free inline: implemented per kernel
// (qkv / oproj differ only in source pointers and epilogue).

__global__ __launch_bounds__(256, 2)
void qkv_mma(const float* __restrict__ bq, const float* __restrict__ bk,
             const float* __restrict__ bv)
{
    extern __shared__ char sm[];
    const uint32_t sb = smem_u32(sm);
    const int tid = threadIdx.x;
    const int lane = tid & 31;
    const int w = tid >> 5, wm = w >> 1, wn = w & 1;
    const int m0 = blockIdx.x * 128;
    const int mat = blockIdx.y >> 3;           // 0=q 1=k 2=v
    const int jt  = blockIdx.y & 7;            // head index (n-tile of 64)
    const int j0  = jt * 64;
    const size_t matoff = (size_t)mat * 262144;
    const __nv_bfloat16* Wh = g_wh + matoff;
    const __nv_bfloat16* Wl = g_wl + matoff;

    float acc[2][4][4];
#pragma unroll
    for (int mi = 0; mi < 2; ++mi)
#pragma unroll
        for (int nt = 0; nt < 4; ++nt)
#pragma unroll
            for (int j = 0; j < 4; ++j) acc[mi][nt][j] = 0.f;

    // lane-fixed ldmatrix addresses (same verified patterns as attn)
    const uint32_t aoff = (wm * 32 + ((lane >> 3) & 1) * 8 + (lane & 7)) * 80
                        + ((lane >> 4) * 8) * 2;
    const uint32_t boff = (wn * 32 + (lane >> 4) * 8 + (lane & 7)) * 80
                        + (((lane >> 3) & 1) * 8) * 2;

    // prologue: chunk 0 -> buffer 0   (1536 cp16 = 6/thread)
#pragma unroll
    for (int i = 0; i < 6; ++i) {
        int e = tid + 256 * i;
        if (e < 1024) {
            int sel = e >> 9, ee = e & 511, row = ee >> 2, u = ee & 3;
            cp16(sb + sel * GM_AL + row * 80 + u * 16,
                 (sel ? g_xl : g_xh) + (size_t)(m0 + row) * CD + u * 8);
        } else {
            int ee = e - 1024, sel = ee >> 8, e2 = ee & 255, row = e2 >> 2, u = e2 & 3;
            cp16(sb + GM_B + sel * GM_BL + row * 80 + u * 16,
                 (sel ? Wl : Wh) + (size_t)(j0 + row) * CD + u * 8);
        }
    }
    CP_COMMIT();

    for (int t = 0; t < 16; ++t) {
        const int buf = t & 1;
        __syncthreads();
        if (t < 15) {
            const int k1 = (t + 1) * 32, nbuf = (t + 1) & 1;
#pragma unroll
            for (int i = 0; i < 6; ++i) {
                int e = tid + 256 * i;
                if (e < 1024) {
                    int sel = e >> 9, ee = e & 511, row = ee >> 2, u = ee & 3;
                    cp16(sb + nbuf * GM_BUF + sel * GM_AL + row * 80 + u * 16,
                         (sel ? g_xl : g_xh) + (size_t)(m0 + row) * CD + k1 + u * 8);
                } else {
                    int ee = e - 1024, sel = ee >> 8, e2 = ee & 255, row = e2 >> 2, u = e2 & 3;
                    cp16(sb + nbuf * GM_BUF + GM_B + sel * GM_BL + row * 80 + u * 16,
                         (sel ? Wl : Wh) + (size_t)(j0 + row) * CD + k1 + u * 8);
                }
            }
        }
        CP_COMMIT();
        CP_WAIT1();
        __syncthreads();

        const uint32_t bA = sb + buf * GM_BUF;
        const uint32_t bB = sb + buf * GM_BUF + GM_B;
#pragma unroll
        for (int ks = 0; ks < 2; ++ks) {
            uint32_t ah[2][4], al[2][4];
#pragma unroll
            for (int mi = 0; mi < 2; ++mi) {
                LDSM4(ah[mi][0], ah[mi][1], ah[mi][2], ah[mi][3],
                      bA + aoff + mi * 16 * 80 + ks * 32);
                LDSM4(al[mi][0], al[mi][1], al[mi][2], al[mi][3],
                      bA + GM_AL + aoff + mi * 16 * 80 + ks * 32);
            }
#pragma unroll
            for (int ntp = 0; ntp < 2; ++ntp) {
                uint32_t bh0, bh1, bh2, bh3, bl0, bl1, bl2, bl3;
                uint32_t ba = bB + boff + ntp * 16 * 80 + ks * 32;
                LDSM4(bh0, bh1, bh2, bh3, ba);
                LDSM4(bl0, bl1, bl2, bl3, ba + GM_BL);
#pragma unroll
                for (int mi = 0; mi < 2; ++mi) {
                    MMA16816(acc[mi][2 * ntp], ah[mi][0], ah[mi][1], ah[mi][2], ah[mi][3], bh0, bh1);
                    MMA16816(acc[mi][2 * ntp], ah[mi][0], ah[mi][1], ah[mi][2], ah[mi][3], bl0, bl1);
                    MMA16816(acc[mi][2 * ntp], al[mi][0], al[mi][1], al[mi][2], al[mi][3], bh0, bh1);
                    MMA16816(acc[mi][2 * ntp + 1], ah[mi][0], ah[mi][1], ah[mi][2], ah[mi][3], bh2, bh3);
                    MMA16816(acc[mi][2 * ntp + 1], ah[mi][0], ah[mi][1], ah[mi][2], ah[mi][3], bl2, bl3);
                    MMA16816(acc[mi][2 * ntp + 1], al[mi][0], al[mi][1], al[mi][2], al[mi][3], bh2, bh3);
                }
            }
        }
    }
    __syncthreads();

    // acc -> smem f32 [128][68]
    float* Outf = (float*)sm;
    const int arow = wm * 32 + (lane >> 2);
    const int acol = wn * 32 + (lane & 3) * 2;
#pragma unroll
    for (int mi = 0; mi < 2; ++mi)
#pragma unroll
        for (int nt = 0; nt < 4; ++nt) {
            int rr = arow + mi * 16;
            int cc = acol + nt * 8;
            Outf[rr * 68 + cc]           = acc[mi][nt][0];
            Outf[rr * 68 + cc + 1]       = acc[mi][nt][1];
            Outf[(rr + 8) * 68 + cc]     = acc[mi][nt][2];
            Outf[(rr + 8) * 68 + cc + 1] = acc[mi][nt][3];
        }
    __syncthreads();

    // bias (+0.125 for Q) + split-bf16 to [nh][s][d]
    const float* bias = (mat == 0) ? bq : (mat == 1) ? bk : bv;
    __nv_bfloat16* dh = (mat == 0) ? g_qh : (mat == 1) ? g_kh : g_vh;
    __nv_bfloat16* dl = (mat == 0) ? g_ql : (mat == 1) ? g_kl : g_vl;
    const float scale = (mat == 0) ? 0.125f : 1.0f;
    const int n = m0 >> 10, s0 = m0 & 1023;
    const int r = tid >> 1, ch = (tid & 1) * 32;
    size_t base = ((size_t)(n * NHD + jt) * SD + s0 + r) * HD + ch;
#pragma unroll
    for (int c = 0; c < 32; c += 2) {
        float v0 = (Outf[r * 68 + ch + c]     + __ldg(bias + j0 + ch + c))     * scale;
        float v1 = (Outf[r * 68 + ch + c + 1] + __ldg(bias + j0 + ch + c + 1)) * scale;
        uint32_t hi, lo; split2(v0, v1, hi, lo);
        *(uint32_t*)(dh + base + c) = hi;
        *(uint32_t*)(dl + base + c) = lo;
    }
}

// ---------------------------------------------------------------------------
// Kernel 2: attention — unchanged from R15/R16 (160 us, 53% tensor).
// ---------------------------------------------------------------------------
#define AT_QH  0
#define AT_K   18432
#define AT_V   55296
#define AT_LS  92160
#define AT_OB  93184
#define AT_SMEM 110592

__global__ __launch_bounds__(256, 2)
void attn_mma()
{
    extern __shared__ char sm[];
    const uint32_t sb = smem_u32(sm);
    const int tid = threadIdx.x;
    const int lane = tid & 31;
    const int w = tid >> 5, wm = w >> 1, wn = w & 1;
    const int nh = blockIdx.y;
    const int s0 = blockIdx.x * 64;
    const size_t qb = ((size_t)nh * SD + s0) * HD;
    const size_t kb = (size_t)nh * SD * HD;

#pragma unroll
    for (int i = 0; i < 4; ++i) {
        int e = tid + 256 * i;
        int sel = e >> 9, ee = e & 511, row = ee >> 3, u = ee & 7;
        cp16(sb + AT_QH + sel * 9216 + row * 144 + u * 16,
             (sel ? g_ql : g_qh) + qb + (size_t)row * HD + u * 8);
        cp16(sb + AT_K + sel * 9216 + row * 144 + u * 16,
             (sel ? g_kl : g_kh) + kb + (size_t)row * HD + u * 8);
        cp16(sb + AT_V + sel * 9216 + row * 144 + u * 16,
             (sel ? g_vl : g_vh) + kb + (size_t)row * HD + u * 8);
    }
    CP_COMMIT();

    float oacc[8][4];
#pragma unroll
    for (int d = 0; d < 8; ++d)
#pragma unroll
        for (int j = 0; j < 4; ++j) oacc[d][j] = 0.f;
    float ps0 = 0.f, ps1 = 0.f;

    const uint32_t qa_h = sb + AT_QH +
        (wm * 16 + ((lane >> 3) & 1) * 8 + (lane & 7)) * 144 + ((lane >> 4) * 8) * 2;
    const uint32_t ka_row = (wn * 32 + (lane >> 4) * 8 + (lane & 7));
    const uint32_t ka_col = (((lane >> 3) & 1) * 8) * 2;
    const uint32_t va_row = (wn * 32 + (lane & 15));
    const uint32_t va_col = (((lane >> 4) & 1) * 8) * 2;

    for (int t = 0; t < 16; ++t) {
        const int buf = t & 1;
        __syncthreads();
        if (t < 15) {
            const int c1 = (t + 1) * 64, nbuf = (t + 1) & 1;
#pragma unroll
            for (int i = 0; i < 4; ++i) {
                int e = tid + 256 * i;
                int sel = e >> 9, ee = e & 511, row = ee >> 3, u = ee & 7;
                cp16(sb + AT_K + nbuf * 18432 + sel * 9216 + row * 144 + u * 16,
                     (sel ? g_kl : g_kh) + kb + (size_t)(c1 + row) * HD + u * 8);
                cp16(sb + AT_V + nbuf * 18432 + sel * 9216 + row * 144 + u * 16,
                     (sel ? g_vl : g_vh) + kb + (size_t)(c1 + row) * HD + u * 8);
            }
        }
        CP_COMMIT();
        CP_WAIT1();
        __syncthreads();

        const uint32_t bK = sb + AT_K + buf * 18432;
        const uint32_t bV = sb + AT_V + buf * 18432;

        float sacc[4][4];
#pragma unroll
        for (int nt = 0; nt < 4; ++nt)
#pragma unroll
            for (int j = 0; j < 4; ++j) sacc[nt][j] = 0.f;

#pragma unroll
        for (int ks = 0; ks < 4; ++ks) {
            uint32_t qh0, qh1, qh2, qh3, ql0, ql1, ql2, ql3;
            LDSM4(qh0, qh1, qh2, qh3, qa_h + ks * 32);
            LDSM4(ql0, ql1, ql2, ql3, qa_h + 9216 + ks * 32);
#pragma unroll
            for (int ntp = 0; ntp < 2; ++ntp) {
                uint32_t kh0, kh1, kh2, kh3, kl0, kl1, kl2, kl3;
                uint32_t ka = bK + (ka_row + ntp * 16) * 144 + ka_col + ks * 32;
                LDSM4(kh0, kh1, kh2, kh3, ka);
                LDSM4(kl0, kl1, kl2, kl3, ka + 9216);
                MMA16816(sacc[2 * ntp],     qh0, qh1, qh2, qh3, kh0, kh1);
                MMA16816(sacc[2 * ntp],     qh0, qh1, qh2, qh3, kl0, kl1);
                MMA16816(sacc[2 * ntp],     ql0, ql1, ql2, ql3, kh0, kh1);
                MMA16816(sacc[2 * ntp + 1], qh0, qh1, qh2, qh3, kh2, kh3);
                MMA16816(sacc[2 * ntp + 1], qh0, qh1, qh2, qh3, kl2, kl3);
                MMA16816(sacc[2 * ntp + 1], ql0, ql1, ql2, ql3, kh2, kh3);
            }
        }

        uint32_t ph[2][4], pl[2][4];
#pragma unroll
        for (int nt = 0; nt < 4; ++nt) {
            float e0 = __expf(sacc[nt][0]);
            float e1 = __expf(sacc[nt][1]);
            float e2 = __expf(sacc[nt][2]);
            float e3 = __expf(sacc[nt][3]);
            ps0 += e0 + e1;
            ps1 += e2 + e3;
            const int kt = nt >> 1, hf = (nt & 1) * 2;
            split2(e0, e1, ph[kt][hf],     pl[kt][hf]);
            split2(e2, e3, ph[kt][hf + 1], pl[kt][hf + 1]);
        }

#pragma unroll
        for (int kt = 0; kt < 2; ++kt) {
#pragma unroll
            for (int dtp = 0; dtp < 4; ++dtp) {
                uint32_t vh0, vh1, vh2, vh3, vl0, vl1, vl2, vl3;
                uint32_t va = bV + (va_row + kt * 16) * 144 + va_col + dtp * 32;
                LDSM4T(vh0, vh1, vh2, vh3, va);
                LDSM4T(vl0, vl1, vl2, vl3, va + 9216);
                const int dt = dtp * 2;
                MMA16816(oacc[dt],     ph[kt][0], ph[kt][1], ph[kt][2], ph[kt][3], vh0, vh1);
                MMA16816(oacc[dt],     ph[kt][0], ph[kt][1], ph[kt][2], ph[kt][3], vl0, vl1);
                MMA16816(oacc[dt],     pl[kt][0], pl[kt][1], pl[kt][2], pl[kt][3], vh0, vh1);
                MMA16816(oacc[dt + 1], ph[kt][0], ph[kt][1], ph[kt][2], ph[kt][3], vh2, vh3);
                MMA16816(oacc[dt + 1], ph[kt][0], ph[kt][1], ph[kt][2], ph[kt][3], vl2, vl3);
                MMA16816(oacc[dt + 1], pl[kt][0], pl[kt][1], pl[kt][2], pl[kt][3], vh2, vh3);
            }
        }
    }

    ps0 += __shfl_xor_sync(0xffffffffu, ps0, 1);
    ps0 += __shfl_xor_sync(0xffffffffu, ps0, 2);
    ps1 += __shfl_xor_sync(0xffffffffu, ps1, 1);
    ps1 += __shfl_xor_sync(0xffffffffu, ps1, 2);
    float* ls = (float*)(sm + AT_LS);
    if ((lane & 3) == 0) {
        ls[wn * 64 + wm * 16 + (lane >> 2)]     = ps0;
        ls[wn * 64 + wm * 16 + (lane >> 2) + 8] = ps1;
    }

    float* Ob = (float*)(sm + AT_OB);   // [64][68]
    const int orow = wm * 16 + (lane >> 2);
    const int ocol = (lane & 3) * 2;
    __syncthreads();
    if (wn == 0) {
#pragma unroll
        for (int dt = 0; dt < 8; ++dt) {
            Ob[orow * 68 + dt * 8 + ocol]           = oacc[dt][0];
            Ob[orow * 68 + dt * 8 + ocol + 1]       = oacc[dt][1];
            Ob[(orow + 8) * 68 + dt * 8 + ocol]     = oacc[dt][2];
            Ob[(orow + 8) * 68 + dt * 8 + ocol + 1] = oacc[dt][3];
        }
    }
    __syncthreads();
    if (wn == 1) {
#pragma unroll
        for (int dt = 0; dt < 8; ++dt) {
            Ob[orow * 68 + dt * 8 + ocol]           += oacc[dt][0];
            Ob[orow * 68 + dt * 8 + ocol + 1]       += oacc[dt][1];
            Ob[(orow + 8) * 68 + dt * 8 + ocol]     += oacc[dt][2];
            Ob[(orow + 8) * 68 + dt * 8 + ocol + 1] += oacc[dt][3];
        }
    }
    __syncthreads();

    const int r = tid >> 2, ch = (tid & 3) * 16;
    const float inv = 1.0f / (ls[r] + ls[64 + r]);
    size_t base = qb + (size_t)r * HD + ch;
#pragma unroll
    for (int c = 0; c < 16; c += 2) {
        float v0 = Ob[r * 68 + ch + c] * inv;
        float v1 = Ob[r * 68 + ch + c + 1] * inv;
        uint32_t hi, lo; split2(v0, v1, hi, lo);
        *(uint32_t*)(g_aoh + base + c) = hi;
        *(uint32_t*)(g_aol + base + c) = lo;
    }
}

// ---------------------------------------------------------------------------
// Kernel 3: output projection — raw mma.sync, same structure as qkv_mma.
// ---------------------------------------------------------------------------
__global__ __launch_bounds__(256, 2)
void oproj_mma(const float* __restrict__ bo, float* __restrict__ out)
{
    extern __shared__ char sm[];
    const uint32_t sb = smem_u32(sm);
    const int tid = threadIdx.x;
    const int lane = tid & 31;
    const int w = tid >> 5, wm = w >> 1, wn = w & 1;
    const int m0 = blockIdx.x * 128;
    const int j0 = blockIdx.y * 64;
    const __nv_bfloat16* Wh = g_wh + (size_t)3 * 262144;
    const __nv_bfloat16* Wl = g_wl + (size_t)3 * 262144;

    float acc[2][4][4];
#pragma unroll
    for (int mi = 0; mi < 2; ++mi)
#pragma unroll
        for (int nt = 0; nt < 4; ++nt)
#pragma unroll
            for (int j = 0; j < 4; ++j) acc[mi][nt][j] = 0.f;

    const uint32_t aoff = (wm * 32 + ((lane >> 3) & 1) * 8 + (lane & 7)) * 80
                        + ((lane >> 4) * 8) * 2;
    const uint32_t boff = (wn * 32 + (lane >> 4) * 8 + (lane & 7)) * 80
                        + (((lane >> 3) & 1) * 8) * 2;

#pragma unroll
    for (int i = 0; i < 6; ++i) {
        int e = tid + 256 * i;
        if (e < 1024) {
            int sel = e >> 9, ee = e & 511, row = ee >> 2, u = ee & 3;
            cp16(sb + sel * GM_AL + row * 80 + u * 16,
                 (sel ? g_aol : g_aoh) + (size_t)(m0 + row) * CD + u * 8);
        } else {
            int ee = e - 1024, sel = ee >> 8, e2 = ee & 255, row = e2 >> 2, u = e2 & 3;
            cp16(sb + GM_B + sel * GM_BL + row * 80 + u * 16,
                 (sel ? Wl : Wh) + (size_t)(j0 + row) * CD + u * 8);
        }
    }
    CP_COMMIT();

    for (int t = 0; t < 16; ++t) {
        const int buf = t & 1;
        __syncthreads();
        if (t < 15) {
            const int k1 = (t + 1) * 32, nbuf = (t + 1) & 1;
#pragma unroll
            for (int i = 0; i < 6; ++i) {
                int e = tid + 256 * i;
                if (e < 1024) {
                    int sel = e >> 9, ee = e & 511, row = ee >> 2, u = ee & 3;
                    cp16(sb + nbuf * GM_BUF + sel * GM_AL + row * 80 + u * 16,
                         (sel ? g_aol : g_aoh) + (size_t)(m0 + row) * CD + k1 + u * 8);
                } else {
                    int ee = e - 1024, sel = ee >> 8, e2 = ee & 255, row = e2 >> 2, u = e2 & 3;
                    cp16(sb + nbuf * GM_BUF + GM_B + sel * GM_BL + row * 80 + u * 16,
                         (sel ? Wl : Wh) + (size_t)(j0 + row) * CD + k1 + u * 8);
                }
            }
        }
        CP_COMMIT();
        CP_WAIT1();
        __syncthreads();

        const uint32_t bA = sb + buf * GM_BUF;
        const uint32_t bB = sb + buf * GM_BUF + GM_B;
#pragma unroll
        for (int ks = 0; ks < 2; ++ks) {
            uint32_t ah[2][4], al[2][4];
#pragma unroll
            for (int mi = 0; mi < 2; ++mi) {
                LDSM4(ah[mi][0], ah[mi][1], ah[mi][2], ah[mi][3],
                      bA + aoff + mi * 16 * 80 + ks * 32);
                LDSM4(al[mi][0], al[mi][1], al[mi][2], al[mi][3],
                      bA + GM_AL + aoff + mi * 16 * 80 + ks * 32);
            }
#pragma unroll
            for (int ntp = 0; ntp < 2; ++ntp) {
                uint32_t bh0, bh1, bh2, bh3, bl0, bl1, bl2, bl3;
                uint32_t ba = bB + boff + ntp * 16 * 80 + ks * 32;
                LDSM4(bh0, bh1, bh2, bh3, ba);
                LDSM4(bl0, bl1, bl2, bl3, ba + GM_BL);
#pragma unroll
                for (int mi = 0; mi < 2; ++mi) {
                    MMA16816(acc[mi][2 * ntp], ah[mi][0], ah[mi][1], ah[mi][2], ah[mi][3], bh0, bh1);
                    MMA16816(acc[mi][2 * ntp], ah[mi][0], ah[mi][1], ah[mi][2], ah[mi][3], bl0, bl1);
                    MMA16816(acc[mi][2 * ntp], al[mi][0], al[mi][1], al[mi][2], al[mi][3], bh0, bh1);
                    MMA16816(acc[mi][2 * ntp + 1], ah[mi][0], ah[mi][1], ah[mi][2], ah[mi][3], bh2, bh3);
                    MMA16816(acc[mi][2 * ntp + 1], ah[mi][0], ah[mi][1], ah[mi][2], ah[mi][3], bl2, bl3);
                    MMA16816(acc[mi][2 * ntp + 1], al[mi][0], al[mi][1], al[mi][2], al[mi][3], bh2, bh3);
                }
            }
        }
    }
    __syncthreads();

    float* Outf = (float*)sm;   // [128][68]
    const int arow = wm * 32 + (lane >> 2);
    const int acol = wn * 32 + (lane & 3) * 2;
#pragma unroll
    for (int mi = 0; mi < 2; ++mi)
#pragma unroll
        for (int nt = 0; nt < 4; ++nt) {
            int rr = arow + mi * 16;
            int cc = acol + nt * 8;
            Outf[rr * 68 + cc]           = acc[mi][nt][0];
            Outf[rr * 68 + cc + 1]       = acc[mi][nt][1];
            Outf[(rr + 8) * 68 + cc]     = acc[mi][nt][2];
            Outf[(rr + 8) * 68 + cc + 1] = acc[mi][nt][3];
        }
    __syncthreads();

    const int r = tid >> 1, ch = (tid & 1) * 32;
    float* ob = out + (size_t)(m0 + r) * CD + j0 + ch;
#pragma unroll
    for (int c = 0; c < 32; c += 4) {
        float4 v;
        v.x = Outf[r * 68 + ch + c]     + __ldg(bo + j0 + ch + c);
        v.y = Outf[r * 68 + ch + c + 1] + __ldg(bo + j0 + ch + c + 1);
        v.z = Outf[r * 68 + ch + c + 2] + __ldg(bo + j0 + ch + c + 2);
        v.w = Outf[r * 68 + ch + c + 3] + __ldg(bo + j0 + ch + c + 3);
        *(float4*)(ob + c) = v;
    }
}

// ---------------------------------------------------------------------------
extern "C" void kernel_launch(void* const* d_in, const int* in_sizes, int n_in,
                              void* d_out, int out_size)
{
    const float* x  = (const float*)d_in[0];
    const float* Wq = (const float*)d_in[1];
    const float* bq = (const float*)d_in[2];
    const float* Wk = (const float*)d_in[3];
    const float* bk = (const float*)d_in[4];
    const float* Wv = (const float*)d_in[5];
    const float* bv = (const float*)d_in[6];
    const float* Wo = (const float*)d_in[7];
    const float* bo = (const float*)d_in[8];
    float* out = (float*)d_out;
    (void)in_sizes; (void)n_in; (void)out_size;

    cudaFuncSetAttribute(qkv_mma,   cudaFuncAttributeMaxDynamicSharedMemorySize, GM_SMEM);
    cudaFuncSetAttribute(attn_mma,  cudaFuncAttributeMaxDynamicSharedMemorySize, AT_SMEM);
    cudaFuncSetAttribute(oproj_mma, cudaFuncAttributeMaxDynamicSharedMemorySize, GM_SMEM);

    split_w<<<512, 256>>>(Wq, Wk, Wv, Wo);
    split_x<<<dim3(16, 32, 8), 256>>>(x);
    qkv_mma<<<dim3(64, 24), 256, GM_SMEM>>>(bq, bk, bv);
    attn_mma<<<dim3(16, 64), 256, AT_SMEM>>>();
    oproj_mma<<<dim3(64, 8), 256, GM_SMEM>>>(bo, out);
}